// round 6
// baseline (speedup 1.0000x reference)
#include <cuda_runtime.h>
#include <cuda_bf16.h>
#include <cuda_fp8.h>
#include <cstdint>

#define N 4096
#define D 1024
#define EPSV 1e-8f
#define MARGIN 0.1f

#define BM 128
#define BN 128
#define BK 128         // 128 fp8 = 128 B per smem row (SW128 atom)
#define NKC (D / BK)   // 8 k-chunks
#define NCTAS ((N / BM) * (N / BN))   // 1024

// ---------------- device globals (scratch) -----------------------------------
__device__ float  g_nw[N];
__device__ float  g_no[N];
__device__ float  g_d[N];
__device__ double g_acc = 0.0;
__device__ unsigned int g_ticket = 0;
__device__ uint8_t g_Wf8[(size_t)N * D];
__device__ uint8_t g_Of8[(size_t)N * D];

// ---------------- helpers ----------------------------------------------------
__device__ __forceinline__ uint32_t smem_u32(const void* p) {
    uint32_t a;
    asm("{ .reg .u64 t; cvta.to.shared.u64 t, %1; cvt.u32.u64 %0, t; }" : "=r"(a) : "l"(p));
    return a;
}
__device__ __forceinline__ float warp_sum(float v) {
    #pragma unroll
    for (int off = 16; off > 0; off >>= 1) v += __shfl_down_sync(0xFFFFFFFFu, v, off);
    return v;
}
__device__ __forceinline__ uint32_t swz128(uint32_t off) { return off ^ ((off >> 3) & 0x70); }

__device__ __forceinline__ void cp_async16(uint32_t saddr, const void* gaddr) {
    asm volatile("cp.async.cg.shared.global [%0], [%1], 16;" :: "r"(saddr), "l"(gaddr));
}
#define CP_COMMIT() asm volatile("cp.async.commit_group;" ::: "memory")
#define CP_WAIT1()  asm volatile("cp.async.wait_group 1;" ::: "memory")
#define CP_WAIT0()  asm volatile("cp.async.wait_group 0;" ::: "memory")

__device__ __forceinline__ void ldsm_x4(uint32_t* r, uint32_t addr) {
    asm volatile("ldmatrix.sync.aligned.m8n8.x4.shared.b16 {%0,%1,%2,%3}, [%4];"
                 : "=r"(r[0]), "=r"(r[1]), "=r"(r[2]), "=r"(r[3]) : "r"(addr));
}
// fp8 e4m3 MMA: m16n8k32, fp32 accum
__device__ __forceinline__ void mma_fp8(float* c, const uint32_t* a, const uint32_t* b) {
    asm volatile(
        "mma.sync.aligned.m16n8k32.row.col.f32.e4m3.e4m3.f32 "
        "{%0,%1,%2,%3}, {%4,%5,%6,%7}, {%8,%9}, {%0,%1,%2,%3};"
        : "+f"(c[0]), "+f"(c[1]), "+f"(c[2]), "+f"(c[3])
        : "r"(a[0]), "r"(a[1]), "r"(a[2]), "r"(a[3]), "r"(b[0]), "r"(b[1]));
}

__device__ __forceinline__ uint32_t pack_fp8x4(float x, float y, float z, float w) {
    __nv_fp8x2_storage_t lo = __nv_cvt_float2_to_fp8x2(make_float2(x, y), __NV_SATFINITE, __NV_E4M3);
    __nv_fp8x2_storage_t hi = __nv_cvt_float2_to_fp8x2(make_float2(z, w), __NV_SATFINITE, __NV_E4M3);
    return (uint32_t)lo | ((uint32_t)hi << 16);
}

// ---------------- kernel 1: row stats (fp32 exact) + fp32->fp8 ---------------
__global__ void row_stats_kernel(const float* __restrict__ W, const float* __restrict__ O) {
    const int t    = threadIdx.x;
    const int half = t >> 7;
    const int tt   = t & 127;
    const int row  = blockIdx.x * 2 + half;

    const float4* W4 = reinterpret_cast<const float4*>(W + (size_t)row * D);
    const float4* O4 = reinterpret_cast<const float4*>(O + (size_t)row * D);
    const float4 a0 = W4[tt], a1 = W4[tt + 128];
    const float4 b0 = O4[tt], b1 = O4[tt + 128];

    uint32_t* Wp = reinterpret_cast<uint32_t*>(g_Wf8 + (size_t)row * D);
    uint32_t* Op = reinterpret_cast<uint32_t*>(g_Of8 + (size_t)row * D);
    Wp[tt]       = pack_fp8x4(a0.x, a0.y, a0.z, a0.w);
    Wp[tt + 128] = pack_fp8x4(a1.x, a1.y, a1.z, a1.w);
    Op[tt]       = pack_fp8x4(b0.x, b0.y, b0.z, b0.w);
    Op[tt + 128] = pack_fp8x4(b1.x, b1.y, b1.z, b1.w);

    float ww = a0.x*a0.x + a0.y*a0.y + a0.z*a0.z + a0.w*a0.w
             + a1.x*a1.x + a1.y*a1.y + a1.z*a1.z + a1.w*a1.w;
    float oo = b0.x*b0.x + b0.y*b0.y + b0.z*b0.z + b0.w*b0.w
             + b1.x*b1.x + b1.y*b1.y + b1.z*b1.z + b1.w*b1.w;
    float wo = a0.x*b0.x + a0.y*b0.y + a0.z*b0.z + a0.w*b0.w
             + a1.x*b1.x + a1.y*b1.y + a1.z*b1.z + a1.w*b1.w;

    ww = warp_sum(ww); oo = warp_sum(oo); wo = warp_sum(wo);

    __shared__ float sw[8], so[8], sd[8];
    const int lane = t & 31, wid = t >> 5;
    if (lane == 0) { sw[wid] = ww; so[wid] = oo; sd[wid] = wo; }
    __syncthreads();
    if ((t & 127) == 0) {
        const int base = half * 4;
        float vw = sw[base] + sw[base+1] + sw[base+2] + sw[base+3];
        float vo = so[base] + so[base+1] + so[base+2] + so[base+3];
        float vd = sd[base] + sd[base+1] + sd[base+2] + sd[base+3];
        float nw = sqrtf(vw), no = sqrtf(vo);
        g_nw[row] = nw; g_no[row] = no;
        g_d[row]  = vd / fmaxf(nw * no, EPSV);
    }
}

// ---------------- kernel 2: fp8 mma GEMM, 3-stage pipeline -------------------
// per stage: A 16KB + B 16KB. 3 stages = 96KB + stats -> 2 CTAs/SM
#define A_BYTES  (BM * 128)
#define B_BYTES  (BN * 128)
#define SM_A(s)  ((s) * A_BYTES)
#define SM_B(s)  (3 * A_BYTES + (s) * B_BYTES)
#define SM_NW    (3 * A_BYTES + 3 * B_BYTES)
#define SM_D     (SM_NW + BM * 4)
#define SM_NO    (SM_D  + BM * 4)
#define SM_TOTAL (SM_NO + BN * 4)

__global__ __launch_bounds__(256, 2)
void gemm_loss_mma(float* __restrict__ out) {
    extern __shared__ char smem[];
    const uint32_t sbase = smem_u32(smem);
    const int tid  = threadIdx.x;
    const int wid  = tid >> 5;
    const int lane = tid & 31;
    const int bi = blockIdx.y;
    const int bj = blockIdx.x;
    const int warp_m = wid >> 2;       // 0..1 (64 rows each)
    const int warp_n = wid & 3;        // 0..3 (32 cols each)

    if (tid < 128) {
        reinterpret_cast<float*>(smem + SM_NW)[tid] = g_nw[bi * BM + tid];
        reinterpret_cast<float*>(smem + SM_D )[tid] = g_d [bi * BM + tid];
        reinterpret_cast<float*>(smem + SM_NO)[tid] = g_no[bj * BN + tid];
    }

    const uint8_t* __restrict__ Wt = g_Wf8 + (size_t)(bi * BM) * D;
    const uint8_t* __restrict__ Ot = g_Of8 + (size_t)(bj * BN) * D;

    const int lrow = tid >> 3;     // 0..31 (+32*i)
    const int lcol = tid & 7;      // 16B chunk within 128B row

    float acc[4][4][4];
    #pragma unroll
    for (int f = 0; f < 4; ++f)
        #pragma unroll
        for (int g = 0; g < 4; ++g)
            #pragma unroll
            for (int r = 0; r < 4; ++r) acc[f][g][r] = 0.f;

    // ldmatrix lane -> address components (same pattern as bf16; 4B groups map
    // onto fp8 k32 fragments 1:1)
    const int a_row = warp_m * 64 + ((lane >> 3) & 1) * 8 + (lane & 7);  // + f*16
    const int a_cb  = (lane >> 4) * 16;                                   // + ks*32
    const int b_row = warp_n * 32 + ((lane >> 4) & 1) * 8 + (lane & 7);  // + nf2*16
    const int b_cb  = ((lane >> 3) & 1) * 16;                             // + ks*32

    // prologue: stages 0,1 for kc=0,1
    #pragma unroll
    for (int kc = 0; kc < 2; ++kc) {
        const int kt = kc * BK;
        const uint32_t sa = sbase + SM_A(kc);
        const uint32_t sb = sbase + SM_B(kc);
        #pragma unroll
        for (int i = 0; i < 4; ++i) {
            int row = lrow + i * 32;
            cp_async16(sa + swz128(row * 128 + lcol * 16),
                       Wt + (size_t)row * D + kt + lcol * 16);
            cp_async16(sb + swz128(row * 128 + lcol * 16),
                       Ot + (size_t)row * D + kt + lcol * 16);
        }
        CP_COMMIT();
    }

    int stage = 0;
    #pragma unroll 1
    for (int kc = 0; kc < NKC; ++kc) {
        if (kc + 1 < NKC) CP_WAIT1(); else CP_WAIT0();
        __syncthreads();

        if (kc + 2 < NKC) {
            const int kt = (kc + 2) * BK;
            const int ns = (stage + 2) % 3;
            const uint32_t sa = sbase + SM_A(ns);
            const uint32_t sb = sbase + SM_B(ns);
            #pragma unroll
            for (int i = 0; i < 4; ++i) {
                int row = lrow + i * 32;
                cp_async16(sa + swz128(row * 128 + lcol * 16),
                           Wt + (size_t)row * D + kt + lcol * 16);
                cp_async16(sb + swz128(row * 128 + lcol * 16),
                           Ot + (size_t)row * D + kt + lcol * 16);
            }
            CP_COMMIT();
        }

        const uint32_t abuf = sbase + SM_A(stage);
        const uint32_t bbuf = sbase + SM_B(stage);

        #pragma unroll
        for (int ks = 0; ks < 4; ++ks) {      // 4 x k32 = 128 per chunk
            uint32_t areg[4][4];
            uint32_t breg[2][4];
            #pragma unroll
            for (int f = 0; f < 4; ++f)
                ldsm_x4(areg[f], abuf + swz128((a_row + f * 16) * 128 + a_cb + ks * 32));
            #pragma unroll
            for (int nf2 = 0; nf2 < 2; ++nf2)
                ldsm_x4(breg[nf2], bbuf + swz128((b_row + nf2 * 16) * 128 + b_cb + ks * 32));
            #pragma unroll
            for (int f = 0; f < 4; ++f)
                #pragma unroll
                for (int g = 0; g < 4; ++g)
                    mma_fp8(acc[f][g], areg[f], &breg[g >> 1][(g & 1) * 2]);
        }
        stage = (stage + 1) % 3;
    }

    // ---- fused epilogue (exact fp32 diagonal) --------------------------------
    const float* snw = reinterpret_cast<const float*>(smem + SM_NW);
    const float* sd  = reinterpret_cast<const float*>(smem + SM_D);
    const float* sno = reinterpret_cast<const float*>(smem + SM_NO);

    const int qrow = lane >> 2;
    const int qcol = (lane & 3) * 2;

    float lsum = 0.f;
    #pragma unroll
    for (int f = 0; f < 4; ++f) {
        const int r0 = warp_m * 64 + f * 16 + qrow;
        #pragma unroll
        for (int half = 0; half < 2; ++half) {
            const int rl = r0 + half * 8;
            const int rg = bi * BM + rl;
            const float nw_r = snw[rl];
            const float d_r  = sd[rl];
            #pragma unroll
            for (int g = 0; g < 4; ++g) {
                #pragma unroll
                for (int e = 0; e < 2; ++e) {
                    const int cl = warp_n * 32 + g * 8 + qcol + e;
                    const int jg = bj * BN + cl;
                    const float S = acc[f][g][half * 2 + e] *
                                    __fdividef(1.0f, fmaxf(nw_r * sno[cl], EPSV));
                    // diagonal: use exact fp32 cosine, not the fp8 GEMM value
                    lsum += (rg == jg) ? (1.0f - d_r) : fmaxf(MARGIN - S + d_r, 0.0f);
                }
            }
        }
    }

    lsum = warp_sum(lsum);
    __shared__ float red[8];
    if (lane == 0) red[wid] = lsum;
    __syncthreads();
    if (wid == 0) {
        float v = (lane < 8) ? red[lane] : 0.f;
        v = warp_sum(v);
        if (lane == 0) {
            atomicAdd(&g_acc, (double)v);
            __threadfence();
            unsigned int t = atomicAdd(&g_ticket, 1u);
            if (t == NCTAS - 1) {
                double total;
                asm volatile("ld.global.acquire.gpu.f64 %0, [%1];" : "=d"(total) : "l"(&g_acc));
                out[0] = (float)(total / ((double)N * (double)N));
                g_acc = 0.0;
                g_ticket = 0u;
                __threadfence();
            }
        }
    }
}

extern "C" void kernel_launch(void* const* d_in, const int* in_sizes, int n_in,
                              void* d_out, int out_size) {
    const float* W = (const float*)d_in[0];
    const float* O = (const float*)d_in[1];
    float* out = (float*)d_out;

    cudaFuncSetAttribute(gemm_loss_mma, cudaFuncAttributeMaxDynamicSharedMemorySize, SM_TOTAL);

    row_stats_kernel<<<N / 2, 256>>>(W, O);

    dim3 grid(N / BN, N / BM);   // (32, 32)
    gemm_loss_mma<<<grid, 256, SM_TOTAL>>>(out);
}

// round 7
// speedup vs baseline: 1.0919x; 1.0919x over previous
#include <cuda_runtime.h>
#include <cuda_fp16.h>
#include <cstdint>

#define N 4096
#define D 1024
#define EPSV 1e-8f
#define MARGIN 0.1f

#define BM 128
#define BN 256
#define BK 64          // 64 fp16 = 128 B per smem row (SW128 atom)
#define NKC (D / BK)   // 16 k-chunks
#define NCTAS ((N / BM) * (N / BN))   // 512

// ---------------- device globals (scratch) -----------------------------------
__device__ float  g_nw[N];
__device__ float  g_no[N];
__device__ float  g_d[N];
__device__ double g_acc = 0.0;
__device__ unsigned int g_ticket = 0;
__device__ __half g_Wh[(size_t)N * D];
__device__ __half g_Oh[(size_t)N * D];

// ---------------- helpers ----------------------------------------------------
__device__ __forceinline__ uint32_t smem_u32(const void* p) {
    uint32_t a;
    asm("{ .reg .u64 t; cvta.to.shared.u64 t, %1; cvt.u32.u64 %0, t; }" : "=r"(a) : "l"(p));
    return a;
}
__device__ __forceinline__ float warp_sum(float v) {
    #pragma unroll
    for (int off = 16; off > 0; off >>= 1) v += __shfl_down_sync(0xFFFFFFFFu, v, off);
    return v;
}
__device__ __forceinline__ uint32_t swz128(uint32_t off) { return off ^ ((off >> 3) & 0x70); }

__device__ __forceinline__ void cp_async16(uint32_t saddr, const void* gaddr) {
    asm volatile("cp.async.cg.shared.global [%0], [%1], 16;" :: "r"(saddr), "l"(gaddr));
}
#define CP_COMMIT() asm volatile("cp.async.commit_group;" ::: "memory")
#define CP_WAIT0()  asm volatile("cp.async.wait_group 0;" ::: "memory")

__device__ __forceinline__ void ldsm_x4(uint32_t* r, uint32_t addr) {
    asm volatile("ldmatrix.sync.aligned.m8n8.x4.shared.b16 {%0,%1,%2,%3}, [%4];"
                 : "=r"(r[0]), "=r"(r[1]), "=r"(r[2]), "=r"(r[3]) : "r"(addr));
}
// fp16 MMA with fp16 accumulators: C frag = 2 regs (4 halves)
__device__ __forceinline__ void mma_f16acc(uint32_t* c, const uint32_t* a, const uint32_t* b) {
    asm volatile(
        "mma.sync.aligned.m16n8k16.row.col.f16.f16.f16.f16 "
        "{%0,%1}, {%2,%3,%4,%5}, {%6,%7}, {%0,%1};"
        : "+r"(c[0]), "+r"(c[1])
        : "r"(a[0]), "r"(a[1]), "r"(a[2]), "r"(a[3]), "r"(b[0]), "r"(b[1]));
}

// ---------------- kernel 1: row stats (fp32 exact) + fp32->fp16 --------------
__global__ void row_stats_kernel(const float* __restrict__ W, const float* __restrict__ O) {
    const int t    = threadIdx.x;
    const int half = t >> 7;
    const int tt   = t & 127;
    const int row  = blockIdx.x * 2 + half;

    const float4* W4 = reinterpret_cast<const float4*>(W + (size_t)row * D);
    const float4* O4 = reinterpret_cast<const float4*>(O + (size_t)row * D);
    const float4 a0 = W4[tt], a1 = W4[tt + 128];
    const float4 b0 = O4[tt], b1 = O4[tt + 128];

    uint2* Wp = reinterpret_cast<uint2*>(g_Wh + (size_t)row * D);
    uint2* Op = reinterpret_cast<uint2*>(g_Oh + (size_t)row * D);
    {
        __half2 x0 = __float22half2_rn(make_float2(a0.x, a0.y));
        __half2 x1 = __float22half2_rn(make_float2(a0.z, a0.w));
        Wp[tt] = make_uint2(*(uint32_t*)&x0, *(uint32_t*)&x1);
        __half2 y0 = __float22half2_rn(make_float2(a1.x, a1.y));
        __half2 y1 = __float22half2_rn(make_float2(a1.z, a1.w));
        Wp[tt + 128] = make_uint2(*(uint32_t*)&y0, *(uint32_t*)&y1);
        __half2 z0 = __float22half2_rn(make_float2(b0.x, b0.y));
        __half2 z1 = __float22half2_rn(make_float2(b0.z, b0.w));
        Op[tt] = make_uint2(*(uint32_t*)&z0, *(uint32_t*)&z1);
        __half2 w0 = __float22half2_rn(make_float2(b1.x, b1.y));
        __half2 w1 = __float22half2_rn(make_float2(b1.z, b1.w));
        Op[tt + 128] = make_uint2(*(uint32_t*)&w0, *(uint32_t*)&w1);
    }

    float ww = a0.x*a0.x + a0.y*a0.y + a0.z*a0.z + a0.w*a0.w
             + a1.x*a1.x + a1.y*a1.y + a1.z*a1.z + a1.w*a1.w;
    float oo = b0.x*b0.x + b0.y*b0.y + b0.z*b0.z + b0.w*b0.w
             + b1.x*b1.x + b1.y*b1.y + b1.z*b1.z + b1.w*b1.w;
    float wo = a0.x*b0.x + a0.y*b0.y + a0.z*b0.z + a0.w*b0.w
             + a1.x*b1.x + a1.y*b1.y + a1.z*b1.z + a1.w*b1.w;

    ww = warp_sum(ww); oo = warp_sum(oo); wo = warp_sum(wo);

    __shared__ float sw[8], so[8], sd[8];
    const int lane = t & 31, wid = t >> 5;
    if (lane == 0) { sw[wid] = ww; so[wid] = oo; sd[wid] = wo; }
    __syncthreads();
    if ((t & 127) == 0) {
        const int base = half * 4;
        float vw = sw[base] + sw[base+1] + sw[base+2] + sw[base+3];
        float vo = so[base] + so[base+1] + so[base+2] + so[base+3];
        float vd = sd[base] + sd[base+1] + sd[base+2] + sd[base+3];
        float nw = sqrtf(vw), no = sqrtf(vo);
        g_nw[row] = nw; g_no[row] = no;
        g_d[row]  = vd / fmaxf(nw * no, EPSV);
    }
}

// ---------------- kernel 2: fp16 mma GEMM, 64x64 warp tiles ------------------
// per stage: A 16KB + B 32KB. 2 stages = 96KB + stats -> 2 CTAs/SM
#define A_BYTES  (BM * 128)                  // 16384
#define B_BYTES  (BN * 128)                  // 32768
#define SM_A(s)  ((s) * A_BYTES)
#define SM_B(s)  (2 * A_BYTES + (s) * B_BYTES)
#define SM_NW    (2 * A_BYTES + 2 * B_BYTES)
#define SM_D     (SM_NW + BM * 4)
#define SM_NO    (SM_D  + BM * 4)
#define SM_TOTAL (SM_NO + BN * 4)

__global__ __launch_bounds__(256, 2)
void gemm_loss_mma(float* __restrict__ out) {
    extern __shared__ char smem[];
    const uint32_t sbase = smem_u32(smem);
    const int tid  = threadIdx.x;
    const int wid  = tid >> 5;
    const int lane = tid & 31;
    const int bi = blockIdx.y;
    const int bj = blockIdx.x;
    const int warp_m = wid >> 2;       // 0..1 (64 rows each)
    const int warp_n = wid & 3;        // 0..3 (64 cols each)

    if (tid < 128) {
        reinterpret_cast<float*>(smem + SM_NW)[tid] = g_nw[bi * BM + tid];
        reinterpret_cast<float*>(smem + SM_D )[tid] = g_d [bi * BM + tid];
    }
    reinterpret_cast<float*>(smem + SM_NO)[tid] = g_no[bj * BN + tid];

    const __half* __restrict__ Wt = g_Wh + (size_t)(bi * BM) * D;
    const __half* __restrict__ Ot = g_Oh + (size_t)(bj * BN) * D;

    const int lrow = tid >> 3;     // 0..31
    const int lcol = tid & 7;      // 16B chunk within 128B row

    // acc[f][g]: f = m16 frag (4), g = n8 frag (8); 2 regs each (f16x2)
    uint32_t acc[4][8][2];
    #pragma unroll
    for (int f = 0; f < 4; ++f)
        #pragma unroll
        for (int g = 0; g < 8; ++g)
            acc[f][g][0] = acc[f][g][1] = 0u;

    const int a_row = warp_m * 64 + ((lane >> 3) & 1) * 8 + (lane & 7);  // + f*16
    const int a_cb  = (lane >> 4) * 16;                                   // + ks*32
    const int b_row = warp_n * 64 + ((lane >> 4) & 1) * 8 + (lane & 7);  // + nf*16
    const int b_cb  = ((lane >> 3) & 1) * 16;                             // + ks*32

    // prologue: chunk 0 into stage 0
    {
        const uint32_t sa = sbase + SM_A(0);
        const uint32_t sb = sbase + SM_B(0);
        #pragma unroll
        for (int i = 0; i < 4; ++i) {
            int row = lrow + i * 32;
            cp_async16(sa + swz128(row * 128 + lcol * 16),
                       Wt + (size_t)row * D + lcol * 8);
        }
        #pragma unroll
        for (int i = 0; i < 8; ++i) {
            int row = lrow + i * 32;
            cp_async16(sb + swz128(row * 128 + lcol * 16),
                       Ot + (size_t)row * D + lcol * 8);
        }
        CP_COMMIT();
    }

    #pragma unroll 1
    for (int kc = 0; kc < NKC; ++kc) {
        const int b = kc & 1;
        CP_WAIT0();
        __syncthreads();

        if (kc + 1 < NKC) {
            const int kt = (kc + 1) * BK;
            const uint32_t sa = sbase + SM_A(b ^ 1);
            const uint32_t sb = sbase + SM_B(b ^ 1);
            #pragma unroll
            for (int i = 0; i < 4; ++i) {
                int row = lrow + i * 32;
                cp_async16(sa + swz128(row * 128 + lcol * 16),
                           Wt + (size_t)row * D + kt + lcol * 8);
            }
            #pragma unroll
            for (int i = 0; i < 8; ++i) {
                int row = lrow + i * 32;
                cp_async16(sb + swz128(row * 128 + lcol * 16),
                           Ot + (size_t)row * D + kt + lcol * 8);
            }
            CP_COMMIT();
        }

        const uint32_t abuf = sbase + SM_A(b);
        const uint32_t bbuf = sbase + SM_B(b);

        #pragma unroll
        for (int ks = 0; ks < 4; ++ks) {      // 4 x k16 = 64 per chunk
            uint32_t areg[4][4];
            uint32_t breg[4][4];
            #pragma unroll
            for (int f = 0; f < 4; ++f)
                ldsm_x4(areg[f], abuf + swz128((a_row + f * 16) * 128 + a_cb + ks * 32));
            #pragma unroll
            for (int nf = 0; nf < 4; ++nf)
                ldsm_x4(breg[nf], bbuf + swz128((b_row + nf * 16) * 128 + b_cb + ks * 32));
            #pragma unroll
            for (int f = 0; f < 4; ++f)
                #pragma unroll
                for (int g = 0; g < 8; ++g)
                    mma_f16acc(acc[f][g], areg[f], &breg[g >> 1][(g & 1) * 2]);
        }
    }

    // ---- fused epilogue (fp32 normalize, exact fp32 diagonal) ----------------
    const float* snw = reinterpret_cast<const float*>(smem + SM_NW);
    const float* sd  = reinterpret_cast<const float*>(smem + SM_D);
    const float* sno = reinterpret_cast<const float*>(smem + SM_NO);

    const int qrow = lane >> 2;
    const int qcol = (lane & 3) * 2;

    float lsum = 0.f;
    #pragma unroll
    for (int f = 0; f < 4; ++f) {
        const int r0 = warp_m * 64 + f * 16 + qrow;
        #pragma unroll
        for (int hf = 0; hf < 2; ++hf) {       // reg0: row, reg1: row+8
            const int rl = r0 + hf * 8;
            const int rg = bi * BM + rl;
            const float nw_r = snw[rl];
            const float d_r  = sd[rl];
            #pragma unroll
            for (int g = 0; g < 8; ++g) {
                const float2 sv = __half22float2(*reinterpret_cast<__half2*>(&acc[f][g][hf]));
                #pragma unroll
                for (int e = 0; e < 2; ++e) {
                    const int cl = warp_n * 64 + g * 8 + qcol + e;
                    const int jg = bj * BN + cl;
                    const float S = (e ? sv.y : sv.x) *
                                    __fdividef(1.0f, fmaxf(nw_r * sno[cl], EPSV));
                    lsum += (rg == jg) ? (1.0f - d_r) : fmaxf(MARGIN - S + d_r, 0.0f);
                }
            }
        }
    }

    lsum = warp_sum(lsum);
    __shared__ float red[8];
    if (lane == 0) red[wid] = lsum;
    __syncthreads();
    if (wid == 0) {
        float v = (lane < 8) ? red[lane] : 0.f;
        v = warp_sum(v);
        if (lane == 0) {
            atomicAdd(&g_acc, (double)v);
            __threadfence();
            unsigned int t = atomicAdd(&g_ticket, 1u);
            if (t == NCTAS - 1) {
                double total;
                asm volatile("ld.global.acquire.gpu.f64 %0, [%1];" : "=d"(total) : "l"(&g_acc));
                out[0] = (float)(total / ((double)N * (double)N));
                g_acc = 0.0;
                g_ticket = 0u;
                __threadfence();
            }
        }
    }
}

extern "C" void kernel_launch(void* const* d_in, const int* in_sizes, int n_in,
                              void* d_out, int out_size) {
    const float* W = (const float*)d_in[0];
    const float* O = (const float*)d_in[1];
    float* out = (float*)d_out;

    cudaFuncSetAttribute(gemm_loss_mma, cudaFuncAttributeMaxDynamicSharedMemorySize, SM_TOTAL);

    row_stats_kernel<<<N / 2, 256>>>(W, O);

    dim3 grid(N / BN, N / BM);   // (16, 32)
    gemm_loss_mma<<<grid, 256, SM_TOTAL>>>(out);
}

// round 8
// speedup vs baseline: 1.2024x; 1.1012x over previous
#include <cuda_runtime.h>
#include <cuda_bf16.h>
#include <cstdint>

#define N 4096
#define D 1024
#define EPSV 1e-8f
#define MARGIN 0.1f

#define BM 128
#define BN 128
#define BK 64          // 64 bf16 = 128 B per smem row (SW128 atom)
#define NKC (D / BK)   // 16 k-chunks
#define NCTAS ((N / BM) * (N / BN))   // 1024

// ---------------- device globals (scratch) -----------------------------------
__device__ float  g_nw[N];
__device__ float  g_no[N];
__device__ float  g_d[N];
__device__ double g_acc = 0.0;
__device__ unsigned int g_ticket = 0;
__device__ __nv_bfloat16 g_Wb[(size_t)N * D];
__device__ __nv_bfloat16 g_Ob[(size_t)N * D];

// ---------------- helpers ----------------------------------------------------
__device__ __forceinline__ uint32_t smem_u32(const void* p) {
    uint32_t a;
    asm("{ .reg .u64 t; cvta.to.shared.u64 t, %1; cvt.u32.u64 %0, t; }" : "=r"(a) : "l"(p));
    return a;
}
__device__ __forceinline__ float warp_sum(float v) {
    #pragma unroll
    for (int off = 16; off > 0; off >>= 1) v += __shfl_down_sync(0xFFFFFFFFu, v, off);
    return v;
}
__device__ __forceinline__ uint32_t swz128(uint32_t off) { return off ^ ((off >> 3) & 0x70); }

__device__ __forceinline__ void cp_async16(uint32_t saddr, const void* gaddr) {
    asm volatile("cp.async.cg.shared.global [%0], [%1], 16;" :: "r"(saddr), "l"(gaddr));
}
#define CP_COMMIT() asm volatile("cp.async.commit_group;" ::: "memory")
#define CP_WAIT2()  asm volatile("cp.async.wait_group 2;" ::: "memory")
#define CP_WAIT1()  asm volatile("cp.async.wait_group 1;" ::: "memory")
#define CP_WAIT0()  asm volatile("cp.async.wait_group 0;" ::: "memory")

__device__ __forceinline__ void ldsm_x4(uint32_t* r, uint32_t addr) {
    asm volatile("ldmatrix.sync.aligned.m8n8.x4.shared.b16 {%0,%1,%2,%3}, [%4];"
                 : "=r"(r[0]), "=r"(r[1]), "=r"(r[2]), "=r"(r[3]) : "r"(addr));
}
__device__ __forceinline__ void mma_bf16(float* c, const uint32_t* a, const uint32_t* b) {
    asm volatile(
        "mma.sync.aligned.m16n8k16.row.col.f32.bf16.bf16.f32 "
        "{%0,%1,%2,%3}, {%4,%5,%6,%7}, {%8,%9}, {%0,%1,%2,%3};"
        : "+f"(c[0]), "+f"(c[1]), "+f"(c[2]), "+f"(c[3])
        : "r"(a[0]), "r"(a[1]), "r"(a[2]), "r"(a[3]), "r"(b[0]), "r"(b[1]));
}

// ---------------- kernel 1: row stats + bf16 convert (4 rows/block, MLP 8) ---
__global__ void row_stats_kernel(const float* __restrict__ W, const float* __restrict__ O) {
    const int t = threadIdx.x;
    const int r = t >> 6;              // 0..3 local row
    const int c = t & 63;              // 64 threads per row
    const int row = blockIdx.x * 4 + r;

    const float4* W4 = reinterpret_cast<const float4*>(W + (size_t)row * D);
    const float4* O4 = reinterpret_cast<const float4*>(O + (size_t)row * D);

    float4 a[4], b[4];
    #pragma unroll
    for (int i = 0; i < 4; ++i) a[i] = W4[c + 64 * i];
    #pragma unroll
    for (int i = 0; i < 4; ++i) b[i] = O4[c + 64 * i];

    uint2* Wp = reinterpret_cast<uint2*>(g_Wb + (size_t)row * D);
    uint2* Op = reinterpret_cast<uint2*>(g_Ob + (size_t)row * D);
    #pragma unroll
    for (int i = 0; i < 4; ++i) {
        __nv_bfloat162 lo = __floats2bfloat162_rn(a[i].x, a[i].y);
        __nv_bfloat162 hi = __floats2bfloat162_rn(a[i].z, a[i].w);
        Wp[c + 64 * i] = make_uint2(*(uint32_t*)&lo, *(uint32_t*)&hi);
    }
    #pragma unroll
    for (int i = 0; i < 4; ++i) {
        __nv_bfloat162 lo = __floats2bfloat162_rn(b[i].x, b[i].y);
        __nv_bfloat162 hi = __floats2bfloat162_rn(b[i].z, b[i].w);
        Op[c + 64 * i] = make_uint2(*(uint32_t*)&lo, *(uint32_t*)&hi);
    }

    float ww = 0.f, oo = 0.f, wo = 0.f;
    #pragma unroll
    for (int i = 0; i < 4; ++i) {
        ww += a[i].x*a[i].x + a[i].y*a[i].y + a[i].z*a[i].z + a[i].w*a[i].w;
        oo += b[i].x*b[i].x + b[i].y*b[i].y + b[i].z*b[i].z + b[i].w*b[i].w;
        wo += a[i].x*b[i].x + a[i].y*b[i].y + a[i].z*b[i].z + a[i].w*b[i].w;
    }
    ww = warp_sum(ww); oo = warp_sum(oo); wo = warp_sum(wo);

    __shared__ float sw[8], so[8], sd[8];
    const int lane = t & 31, wid = t >> 5;   // warp w covers row w>>1
    if (lane == 0) { sw[wid] = ww; so[wid] = oo; sd[wid] = wo; }
    __syncthreads();
    if (c == 0) {   // one thread per row (t = r*64)
        float vw = sw[2*r] + sw[2*r+1];
        float vo = so[2*r] + so[2*r+1];
        float vd = sd[2*r] + sd[2*r+1];
        float nw = sqrtf(vw), no = sqrtf(vo);
        g_nw[row] = nw; g_no[row] = no;
        g_d[row]  = vd / fmaxf(nw * no, EPSV);
    }
}

// ---------------- kernel 2: bf16 mma GEMM, 3-stage prefetch-before-wait ------
#define A_BYTES  (BM * 128)
#define B_BYTES  (BN * 128)
#define SM_A(s)  ((s) * A_BYTES)
#define SM_B(s)  (3 * A_BYTES + (s) * B_BYTES)
#define SM_NW    (3 * A_BYTES + 3 * B_BYTES)
#define SM_D     (SM_NW + BM * 4)
#define SM_NO    (SM_D  + BM * 4)
#define SM_TOTAL (SM_NO + BN * 4)

__global__ __launch_bounds__(256, 2)
void gemm_loss_mma(float* __restrict__ out) {
    extern __shared__ char smem[];
    const uint32_t sbase = smem_u32(smem);
    const int tid  = threadIdx.x;
    const int wid  = tid >> 5;
    const int lane = tid & 31;
    const int bi = blockIdx.y;
    const int bj = blockIdx.x;
    const int warp_m = wid >> 2;       // 0..1 (64 rows each)
    const int warp_n = wid & 3;        // 0..3 (32 cols each)

    if (tid < 128) {
        reinterpret_cast<float*>(smem + SM_NW)[tid] = g_nw[bi * BM + tid];
        reinterpret_cast<float*>(smem + SM_D )[tid] = g_d [bi * BM + tid];
        reinterpret_cast<float*>(smem + SM_NO)[tid] = g_no[bj * BN + tid];
    }

    const __nv_bfloat16* __restrict__ Wt = g_Wb + (size_t)(bi * BM) * D;
    const __nv_bfloat16* __restrict__ Ot = g_Ob + (size_t)(bj * BN) * D;

    const int lrow = tid >> 3;     // 0..31 (+32*i)
    const int lcol = tid & 7;

    float acc[4][4][4];
    #pragma unroll
    for (int f = 0; f < 4; ++f)
        #pragma unroll
        for (int g = 0; g < 4; ++g)
            #pragma unroll
            for (int r = 0; r < 4; ++r) acc[f][g][r] = 0.f;

    const int a_row = warp_m * 64 + ((lane >> 3) & 1) * 8 + (lane & 7);
    const int a_cb  = (lane >> 4) * 16;
    const int b_row = warp_n * 32 + ((lane >> 4) & 1) * 8 + (lane & 7);
    const int b_cb  = ((lane >> 3) & 1) * 16;

    // rotating stage base addresses (no modulo arithmetic in the loop)
    uint32_t sa0 = sbase + SM_A(0), sa1 = sbase + SM_A(1), sa2 = sbase + SM_A(2);
    uint32_t sb0 = sbase + SM_B(0), sb1 = sbase + SM_B(1), sb2 = sbase + SM_B(2);

    // prologue: chunks 0,1 into stages 0,1
    #pragma unroll
    for (int kc = 0; kc < 2; ++kc) {
        const int kt = kc * BK;
        const uint32_t sa = kc ? sa1 : sa0;
        const uint32_t sb = kc ? sb1 : sb0;
        #pragma unroll
        for (int i = 0; i < 4; ++i) {
            int row = lrow + i * 32;
            cp_async16(sa + swz128(row * 128 + lcol * 16),
                       Wt + (size_t)row * D + kt + lcol * 8);
            cp_async16(sb + swz128(row * 128 + lcol * 16),
                       Ot + (size_t)row * D + kt + lcol * 8);
        }
        CP_COMMIT();
    }

    #pragma unroll 1
    for (int kc = 0; kc < NKC; ++kc) {
        // all warps done reading the buffer sa2/sb2 now points at (compute kc-1)
        __syncthreads();

        if (kc + 2 < NKC) {
            const int kt = (kc + 2) * BK;
            #pragma unroll
            for (int i = 0; i < 4; ++i) {
                int row = lrow + i * 32;
                cp_async16(sa2 + swz128(row * 128 + lcol * 16),
                           Wt + (size_t)row * D + kt + lcol * 8);
                cp_async16(sb2 + swz128(row * 128 + lcol * 16),
                           Ot + (size_t)row * D + kt + lcol * 8);
            }
            CP_COMMIT();
            CP_WAIT2();          // chunk kc retired (2 groups still in flight)
        } else if (kc + 1 < NKC) {
            CP_WAIT1();
        } else {
            CP_WAIT0();
        }
        __syncthreads();         // chunk kc visible to all warps

        #pragma unroll
        for (int ks = 0; ks < 4; ++ks) {
            uint32_t areg[4][4];
            uint32_t breg[2][4];
            #pragma unroll
            for (int f = 0; f < 4; ++f)
                ldsm_x4(areg[f], sa0 + swz128((a_row + f * 16) * 128 + a_cb + ks * 32));
            #pragma unroll
            for (int nf2 = 0; nf2 < 2; ++nf2)
                ldsm_x4(breg[nf2], sb0 + swz128((b_row + nf2 * 16) * 128 + b_cb + ks * 32));
            #pragma unroll
            for (int f = 0; f < 4; ++f)
                #pragma unroll
                for (int g = 0; g < 4; ++g)
                    mma_bf16(acc[f][g], areg[f], &breg[g >> 1][(g & 1) * 2]);
        }

        // rotate ring: compute stage advances
        uint32_t ta = sa0; sa0 = sa1; sa1 = sa2; sa2 = ta;
        uint32_t tb = sb0; sb0 = sb1; sb1 = sb2; sb2 = tb;
    }

    // ---- fused epilogue ------------------------------------------------------
    const float* snw = reinterpret_cast<const float*>(smem + SM_NW);
    const float* sd  = reinterpret_cast<const float*>(smem + SM_D);
    const float* sno = reinterpret_cast<const float*>(smem + SM_NO);

    const int qrow = lane >> 2;
    const int qcol = (lane & 3) * 2;

    float lsum = 0.f;
    #pragma unroll
    for (int f = 0; f < 4; ++f) {
        const int r0 = warp_m * 64 + f * 16 + qrow;
        #pragma unroll
        for (int half = 0; half < 2; ++half) {
            const int rl = r0 + half * 8;
            const int rg = bi * BM + rl;
            const float nw_r = snw[rl];
            const float d_r  = sd[rl];
            #pragma unroll
            for (int g = 0; g < 4; ++g) {
                #pragma unroll
                for (int e = 0; e < 2; ++e) {
                    const int cl = warp_n * 32 + g * 8 + qcol + e;
                    const int jg = bj * BN + cl;
                    const float S = acc[f][g][half * 2 + e] *
                                    __fdividef(1.0f, fmaxf(nw_r * sno[cl], EPSV));
                    lsum += (rg == jg) ? (1.0f - d_r) : fmaxf(MARGIN - S + d_r, 0.0f);
                }
            }
        }
    }

    lsum = warp_sum(lsum);
    __shared__ float red[8];
    if (lane == 0) red[wid] = lsum;
    __syncthreads();
    if (wid == 0) {
        float v = (lane < 8) ? red[lane] : 0.f;
        v = warp_sum(v);
        if (lane == 0) {
            atomicAdd(&g_acc, (double)v);
            __threadfence();
            unsigned int t = atomicAdd(&g_ticket, 1u);
            if (t == NCTAS - 1) {
                double total;
                asm volatile("ld.global.acquire.gpu.f64 %0, [%1];" : "=d"(total) : "l"(&g_acc));
                out[0] = (float)(total / ((double)N * (double)N));
                g_acc = 0.0;
                g_ticket = 0u;
                __threadfence();
            }
        }
    }
}

extern "C" void kernel_launch(void* const* d_in, const int* in_sizes, int n_in,
                              void* d_out, int out_size) {
    const float* W = (const float*)d_in[0];
    const float* O = (const float*)d_in[1];
    float* out = (float*)d_out;

    cudaFuncSetAttribute(gemm_loss_mma, cudaFuncAttributeMaxDynamicSharedMemorySize, SM_TOTAL);

    row_stats_kernel<<<N / 4, 256>>>(W, O);

    dim3 grid(N / BN, N / BM);   // (32, 32)
    gemm_loss_mma<<<grid, 256, SM_TOTAL>>>(out);
}

// round 9
// speedup vs baseline: 1.2269x; 1.0204x over previous
#include <cuda_runtime.h>
#include <cuda_bf16.h>
#include <cstdint>

#define N 4096
#define D 1024
#define EPSV 1e-8f
#define MARGIN 0.1f

#define BM 128
#define BN 128
#define BK 64          // 64 bf16 = 128 B per smem row (SW128 atom)
#define NKC (D / BK)   // 16 k-chunks
#define NCTAS ((N / BM) * (N / BN))   // 1024

// ---------------- device globals (scratch) -----------------------------------
__device__ float  g_rnw[N];   // 1 / ||W_i||
__device__ float  g_rno[N];   // 1 / ||O_j||
__device__ float  g_d[N];     // exact fp32 diagonal cosine
__device__ double g_acc = 0.0;
__device__ unsigned int g_ticket = 0;
__device__ __nv_bfloat16 g_Wb[(size_t)N * D];
__device__ __nv_bfloat16 g_Ob[(size_t)N * D];

// ---------------- helpers ----------------------------------------------------
__device__ __forceinline__ uint32_t smem_u32(const void* p) {
    uint32_t a;
    asm("{ .reg .u64 t; cvta.to.shared.u64 t, %1; cvt.u32.u64 %0, t; }" : "=r"(a) : "l"(p));
    return a;
}
__device__ __forceinline__ float warp_sum(float v) {
    #pragma unroll
    for (int off = 16; off > 0; off >>= 1) v += __shfl_down_sync(0xFFFFFFFFu, v, off);
    return v;
}
__device__ __forceinline__ uint32_t swz128(uint32_t off) { return off ^ ((off >> 3) & 0x70); }

__device__ __forceinline__ void cp_async16(uint32_t saddr, const void* gaddr) {
    asm volatile("cp.async.cg.shared.global [%0], [%1], 16;" :: "r"(saddr), "l"(gaddr));
}
#define CP_COMMIT() asm volatile("cp.async.commit_group;" ::: "memory")
#define CP_WAIT0()  asm volatile("cp.async.wait_group 0;" ::: "memory")

__device__ __forceinline__ void ldsm_x4(uint32_t* r, uint32_t addr) {
    asm volatile("ldmatrix.sync.aligned.m8n8.x4.shared.b16 {%0,%1,%2,%3}, [%4];"
                 : "=r"(r[0]), "=r"(r[1]), "=r"(r[2]), "=r"(r[3]) : "r"(addr));
}
__device__ __forceinline__ void mma_bf16(float* c, const uint32_t* a, const uint32_t* b) {
    asm volatile(
        "mma.sync.aligned.m16n8k16.row.col.f32.bf16.bf16.f32 "
        "{%0,%1,%2,%3}, {%4,%5,%6,%7}, {%8,%9}, {%0,%1,%2,%3};"
        : "+f"(c[0]), "+f"(c[1]), "+f"(c[2]), "+f"(c[3])
        : "r"(a[0]), "r"(a[1]), "r"(a[2]), "r"(a[3]), "r"(b[0]), "r"(b[1]));
}

// ---------------- kernel 1: row stats + bf16 convert (4 rows/block, MLP 8) ---
__global__ void row_stats_kernel(const float* __restrict__ W, const float* __restrict__ O) {
    const int t = threadIdx.x;
    const int r = t >> 6;              // 0..3 local row
    const int c = t & 63;              // 64 threads per row
    const int row = blockIdx.x * 4 + r;

    const float4* W4 = reinterpret_cast<const float4*>(W + (size_t)row * D);
    const float4* O4 = reinterpret_cast<const float4*>(O + (size_t)row * D);

    float4 a[4], b[4];
    #pragma unroll
    for (int i = 0; i < 4; ++i) a[i] = W4[c + 64 * i];
    #pragma unroll
    for (int i = 0; i < 4; ++i) b[i] = O4[c + 64 * i];

    uint2* Wp = reinterpret_cast<uint2*>(g_Wb + (size_t)row * D);
    uint2* Op = reinterpret_cast<uint2*>(g_Ob + (size_t)row * D);
    #pragma unroll
    for (int i = 0; i < 4; ++i) {
        __nv_bfloat162 lo = __floats2bfloat162_rn(a[i].x, a[i].y);
        __nv_bfloat162 hi = __floats2bfloat162_rn(a[i].z, a[i].w);
        Wp[c + 64 * i] = make_uint2(*(uint32_t*)&lo, *(uint32_t*)&hi);
    }
    #pragma unroll
    for (int i = 0; i < 4; ++i) {
        __nv_bfloat162 lo = __floats2bfloat162_rn(b[i].x, b[i].y);
        __nv_bfloat162 hi = __floats2bfloat162_rn(b[i].z, b[i].w);
        Op[c + 64 * i] = make_uint2(*(uint32_t*)&lo, *(uint32_t*)&hi);
    }

    float ww = 0.f, oo = 0.f, wo = 0.f;
    #pragma unroll
    for (int i = 0; i < 4; ++i) {
        ww += a[i].x*a[i].x + a[i].y*a[i].y + a[i].z*a[i].z + a[i].w*a[i].w;
        oo += b[i].x*b[i].x + b[i].y*b[i].y + b[i].z*b[i].z + b[i].w*b[i].w;
        wo += a[i].x*b[i].x + a[i].y*b[i].y + a[i].z*b[i].z + a[i].w*b[i].w;
    }
    ww = warp_sum(ww); oo = warp_sum(oo); wo = warp_sum(wo);

    __shared__ float sw[8], so[8], sd[8];
    const int lane = t & 31, wid = t >> 5;
    if (lane == 0) { sw[wid] = ww; so[wid] = oo; sd[wid] = wo; }
    __syncthreads();
    if (c == 0) {
        float vw = sw[2*r] + sw[2*r+1];
        float vo = so[2*r] + so[2*r+1];
        float vd = sd[2*r] + sd[2*r+1];
        float nw = sqrtf(vw), no = sqrtf(vo);
        float prod = fmaxf(nw * no, EPSV);
        g_rnw[row] = 1.0f / nw;
        g_rno[row] = 1.0f / no;
        g_d[row]   = vd / prod;
    }
}

// ---------------- kernel 2: bf16 mma GEMM, 2-stage wait0 (round-3 core) ------
// per CTA: 2x(A 16KB) + 2x(B 16KB) + stats = ~65.5 KB -> 2 CTAs/SM
#define SM_A0    0
#define SM_A1    (SM_A0 + BM * 128)
#define SM_B0    (SM_A1 + BM * 128)
#define SM_B1    (SM_B0 + BN * 128)
#define SM_RNW   (SM_B1 + BN * 128)
#define SM_D     (SM_RNW + BM * 4)
#define SM_RNO   (SM_D  + BM * 4)
#define SM_TOTAL (SM_RNO + BN * 4)

__global__ __launch_bounds__(256, 2)
void gemm_loss_mma(float* __restrict__ out) {
    extern __shared__ char smem[];
    const uint32_t sbase = smem_u32(smem);
    const int tid  = threadIdx.x;
    const int wid  = tid >> 5;
    const int lane = tid & 31;
    const int bi = blockIdx.y;
    const int bj = blockIdx.x;
    const int warp_m = wid >> 2;       // 0..1 (64 rows each)
    const int warp_n = wid & 3;        // 0..3 (32 cols each)

    if (tid < 128) {
        reinterpret_cast<float*>(smem + SM_RNW)[tid] = g_rnw[bi * BM + tid];
        reinterpret_cast<float*>(smem + SM_D  )[tid] = g_d  [bi * BM + tid];
        reinterpret_cast<float*>(smem + SM_RNO)[tid] = g_rno[bj * BN + tid];
    }

    const __nv_bfloat16* __restrict__ Wt = g_Wb + (size_t)(bi * BM) * D;
    const __nv_bfloat16* __restrict__ Ot = g_Ob + (size_t)(bj * BN) * D;

    const int lrow = tid >> 3;     // 0..31 (+32*i)
    const int lcol = tid & 7;

    float acc[4][4][4];
    #pragma unroll
    for (int f = 0; f < 4; ++f)
        #pragma unroll
        for (int g = 0; g < 4; ++g)
            #pragma unroll
            for (int r = 0; r < 4; ++r) acc[f][g][r] = 0.f;

    const int a_row = warp_m * 64 + ((lane >> 3) & 1) * 8 + (lane & 7);
    const int a_cb  = (lane >> 4) * 16;
    const int b_row = warp_n * 32 + ((lane >> 4) & 1) * 8 + (lane & 7);
    const int b_cb  = ((lane >> 3) & 1) * 16;

    // prologue: load chunk 0 into buffer 0
    {
        #pragma unroll
        for (int i = 0; i < 4; ++i) {
            int row = lrow + i * 32;
            cp_async16(sbase + SM_A0 + swz128(row * 128 + lcol * 16),
                       Wt + (size_t)row * D + lcol * 8);
            cp_async16(sbase + SM_B0 + swz128(row * 128 + lcol * 16),
                       Ot + (size_t)row * D + lcol * 8);
        }
        CP_COMMIT();
    }

    #pragma unroll 1
    for (int kc = 0; kc < NKC; ++kc) {
        const int b = kc & 1;
        CP_WAIT0();
        __syncthreads();

        if (kc + 1 < NKC) {
            const int kt = (kc + 1) * BK;
            const uint32_t sa = sbase + (b ? SM_A0 : SM_A1);
            const uint32_t sb = sbase + (b ? SM_B0 : SM_B1);
            #pragma unroll
            for (int i = 0; i < 4; ++i) {
                int row = lrow + i * 32;
                cp_async16(sa + swz128(row * 128 + lcol * 16),
                           Wt + (size_t)row * D + kt + lcol * 8);
                cp_async16(sb + swz128(row * 128 + lcol * 16),
                           Ot + (size_t)row * D + kt + lcol * 8);
            }
            CP_COMMIT();
        }

        const uint32_t abuf = sbase + (b ? SM_A1 : SM_A0);
        const uint32_t bbuf = sbase + (b ? SM_B1 : SM_B0);

        #pragma unroll
        for (int ks = 0; ks < 4; ++ks) {
            uint32_t areg[4][4];
            uint32_t breg[2][4];
            #pragma unroll
            for (int f = 0; f < 4; ++f)
                ldsm_x4(areg[f], abuf + swz128((a_row + f * 16) * 128 + a_cb + ks * 32));
            #pragma unroll
            for (int nf2 = 0; nf2 < 2; ++nf2)
                ldsm_x4(breg[nf2], bbuf + swz128((b_row + nf2 * 16) * 128 + b_cb + ks * 32));
            #pragma unroll
            for (int f = 0; f < 4; ++f)
                #pragma unroll
                for (int g = 0; g < 4; ++g)
                    mma_bf16(acc[f][g], areg[f], &breg[g >> 1][(g & 1) * 2]);
        }
        __syncthreads();
    }

    // ---- fused epilogue: register-cached stats, reciprocal multiply ----------
    const float* srnw = reinterpret_cast<const float*>(smem + SM_RNW);
    const float* sd   = reinterpret_cast<const float*>(smem + SM_D);
    const float* srno = reinterpret_cast<const float*>(smem + SM_RNO);

    const int qrow = lane >> 2;
    const int qcol = (lane & 3) * 2;

    // 8 distinct rows (f x half) and 8 distinct cols (g x e) per thread
    float rnw_v[8], d_v[8], rno_v[8];
    #pragma unroll
    for (int f = 0; f < 4; ++f)
        #pragma unroll
        for (int h = 0; h < 2; ++h) {
            const int rl = warp_m * 64 + f * 16 + qrow + h * 8;
            rnw_v[f * 2 + h] = srnw[rl];
            d_v  [f * 2 + h] = sd[rl];
        }
    #pragma unroll
    for (int g = 0; g < 4; ++g)
        #pragma unroll
        for (int e = 0; e < 2; ++e)
            rno_v[g * 2 + e] = srno[warp_n * 32 + g * 8 + qcol + e];

    float lsum = 0.f;
    #pragma unroll
    for (int f = 0; f < 4; ++f) {
        #pragma unroll
        for (int h = 0; h < 2; ++h) {
            const int rl = warp_m * 64 + f * 16 + qrow + h * 8;
            const int rg = bi * BM + rl;
            const float rnw_r = rnw_v[f * 2 + h];
            const float d_r   = d_v[f * 2 + h];
            #pragma unroll
            for (int g = 0; g < 4; ++g) {
                #pragma unroll
                for (int e = 0; e < 2; ++e) {
                    const int cl = warp_n * 32 + g * 8 + qcol + e;
                    const int jg = bj * BN + cl;
                    const float S = acc[f][g][h * 2 + e] * rnw_r * rno_v[g * 2 + e];
                    lsum += (rg == jg) ? (1.0f - d_r) : fmaxf(MARGIN - S + d_r, 0.0f);
                }
            }
        }
    }

    lsum = warp_sum(lsum);
    __shared__ float red[8];
    if (lane == 0) red[wid] = lsum;
    __syncthreads();
    if (wid == 0) {
        float v = (lane < 8) ? red[lane] : 0.f;
        v = warp_sum(v);
        if (lane == 0) {
            atomicAdd(&g_acc, (double)v);
            __threadfence();
            unsigned int t = atomicAdd(&g_ticket, 1u);
            if (t == NCTAS - 1) {
                double total;
                asm volatile("ld.global.acquire.gpu.f64 %0, [%1];" : "=d"(total) : "l"(&g_acc));
                out[0] = (float)(total / ((double)N * (double)N));
                g_acc = 0.0;
                g_ticket = 0u;
                __threadfence();
            }
        }
    }
}

extern "C" void kernel_launch(void* const* d_in, const int* in_sizes, int n_in,
                              void* d_out, int out_size) {
    const float* W = (const float*)d_in[0];
    const float* O = (const float*)d_in[1];
    float* out = (float*)d_out;

    cudaFuncSetAttribute(gemm_loss_mma, cudaFuncAttributeMaxDynamicSharedMemorySize, SM_TOTAL);

    row_stats_kernel<<<N / 4, 256>>>(W, O);

    dim3 grid(N / BN, N / BM);   // (32, 32)
    gemm_loss_mma<<<grid, 256, SM_TOTAL>>>(out);
}

// round 10
// speedup vs baseline: 1.2386x; 1.0095x over previous
#include <cuda_runtime.h>
#include <cuda_fp16.h>
#include <cstdint>

#define N 4096
#define D 1024
#define EPSV 1e-8f
#define MARGIN 0.1f

#define BM 128
#define BN 128
#define BK 64          // 64 fp16 = 128 B per smem row (SW128 atom)
#define NKC (D / BK)   // 16 k-chunks
#define NCTAS ((N / BM) * (N / BN))   // 1024

// ---------------- device globals (scratch) -----------------------------------
__device__ float  g_rnw[N];   // 1 / ||W_i||
__device__ float  g_rno[N];   // 1 / ||O_j||
__device__ float  g_d[N];     // exact fp32 diagonal cosine
__device__ double g_acc = 0.0;
__device__ unsigned int g_ticket = 0;
__device__ __half g_Wh[(size_t)N * D];
__device__ __half g_Oh[(size_t)N * D];

// ---------------- helpers ----------------------------------------------------
__device__ __forceinline__ uint32_t smem_u32(const void* p) {
    uint32_t a;
    asm("{ .reg .u64 t; cvta.to.shared.u64 t, %1; cvt.u32.u64 %0, t; }" : "=r"(a) : "l"(p));
    return a;
}
__device__ __forceinline__ float warp_sum(float v) {
    #pragma unroll
    for (int off = 16; off > 0; off >>= 1) v += __shfl_down_sync(0xFFFFFFFFu, v, off);
    return v;
}
__device__ __forceinline__ uint32_t swz128(uint32_t off) { return off ^ ((off >> 3) & 0x70); }

__device__ __forceinline__ void cp_async16(uint32_t saddr, const void* gaddr) {
    asm volatile("cp.async.cg.shared.global [%0], [%1], 16;" :: "r"(saddr), "l"(gaddr));
}
#define CP_COMMIT() asm volatile("cp.async.commit_group;" ::: "memory")
#define CP_WAIT0()  asm volatile("cp.async.wait_group 0;" ::: "memory")

__device__ __forceinline__ void ldsm_x4(uint32_t* r, uint32_t addr) {
    asm volatile("ldmatrix.sync.aligned.m8n8.x4.shared.b16 {%0,%1,%2,%3}, [%4];"
                 : "=r"(r[0]), "=r"(r[1]), "=r"(r[2]), "=r"(r[3]) : "r"(addr));
}
// fp16 MMA with fp16 accumulators: C frag = 2 regs (4 halves)
__device__ __forceinline__ void mma_f16acc(uint32_t* c, const uint32_t* a, const uint32_t* b) {
    asm volatile(
        "mma.sync.aligned.m16n8k16.row.col.f16.f16.f16.f16 "
        "{%0,%1}, {%2,%3,%4,%5}, {%6,%7}, {%0,%1};"
        : "+r"(c[0]), "+r"(c[1])
        : "r"(a[0]), "r"(a[1]), "r"(a[2]), "r"(a[3]), "r"(b[0]), "r"(b[1]));
}

// ---------------- kernel 1: row stats + fp16 convert (4 rows/block, MLP 8) ---
__global__ void row_stats_kernel(const float* __restrict__ W, const float* __restrict__ O) {
    const int t = threadIdx.x;
    const int r = t >> 6;              // 0..3 local row
    const int c = t & 63;              // 64 threads per row
    const int row = blockIdx.x * 4 + r;

    const float4* W4 = reinterpret_cast<const float4*>(W + (size_t)row * D);
    const float4* O4 = reinterpret_cast<const float4*>(O + (size_t)row * D);

    float4 a[4], b[4];
    #pragma unroll
    for (int i = 0; i < 4; ++i) a[i] = W4[c + 64 * i];
    #pragma unroll
    for (int i = 0; i < 4; ++i) b[i] = O4[c + 64 * i];

    uint2* Wp = reinterpret_cast<uint2*>(g_Wh + (size_t)row * D);
    uint2* Op = reinterpret_cast<uint2*>(g_Oh + (size_t)row * D);
    #pragma unroll
    for (int i = 0; i < 4; ++i) {
        __half2 lo = __float22half2_rn(make_float2(a[i].x, a[i].y));
        __half2 hi = __float22half2_rn(make_float2(a[i].z, a[i].w));
        Wp[c + 64 * i] = make_uint2(*(uint32_t*)&lo, *(uint32_t*)&hi);
    }
    #pragma unroll
    for (int i = 0; i < 4; ++i) {
        __half2 lo = __float22half2_rn(make_float2(b[i].x, b[i].y));
        __half2 hi = __float22half2_rn(make_float2(b[i].z, b[i].w));
        Op[c + 64 * i] = make_uint2(*(uint32_t*)&lo, *(uint32_t*)&hi);
    }

    float ww = 0.f, oo = 0.f, wo = 0.f;
    #pragma unroll
    for (int i = 0; i < 4; ++i) {
        ww += a[i].x*a[i].x + a[i].y*a[i].y + a[i].z*a[i].z + a[i].w*a[i].w;
        oo += b[i].x*b[i].x + b[i].y*b[i].y + b[i].z*b[i].z + b[i].w*b[i].w;
        wo += a[i].x*b[i].x + a[i].y*b[i].y + a[i].z*b[i].z + a[i].w*b[i].w;
    }
    ww = warp_sum(ww); oo = warp_sum(oo); wo = warp_sum(wo);

    __shared__ float sw[8], so[8], sd[8];
    const int lane = t & 31, wid = t >> 5;
    if (lane == 0) { sw[wid] = ww; so[wid] = oo; sd[wid] = wo; }
    __syncthreads();
    if (c == 0) {
        float vw = sw[2*r] + sw[2*r+1];
        float vo = so[2*r] + so[2*r+1];
        float vd = sd[2*r] + sd[2*r+1];
        float nw = sqrtf(vw), no = sqrtf(vo);
        float prod = fmaxf(nw * no, EPSV);
        g_rnw[row] = 1.0f / nw;
        g_rno[row] = 1.0f / no;
        g_d[row]   = vd / prod;
    }
}

// ---------------- kernel 2: fp16-acc mma GEMM, 2-stage, 3 CTAs/SM ------------
// per CTA: 2x(A 16KB) + 2x(B 16KB) + stats ~= 67 KB -> 3 CTAs/SM (201 KB)
#define SM_A0    0
#define SM_A1    (SM_A0 + BM * 128)
#define SM_B0    (SM_A1 + BM * 128)
#define SM_B1    (SM_B0 + BN * 128)
#define SM_RNW   (SM_B1 + BN * 128)
#define SM_D     (SM_RNW + BM * 4)
#define SM_RNO   (SM_D  + BM * 4)
#define SM_TOTAL (SM_RNO + BN * 4)

__global__ __launch_bounds__(256, 3)
void gemm_loss_mma(float* __restrict__ out) {
    extern __shared__ char smem[];
    const uint32_t sbase = smem_u32(smem);
    const int tid  = threadIdx.x;
    const int wid  = tid >> 5;
    const int lane = tid & 31;
    const int bi = blockIdx.y;
    const int bj = blockIdx.x;
    const int warp_m = wid >> 2;       // 0..1 (64 rows each)
    const int warp_n = wid & 3;        // 0..3 (32 cols each)

    if (tid < 128) {
        reinterpret_cast<float*>(smem + SM_RNW)[tid] = g_rnw[bi * BM + tid];
        reinterpret_cast<float*>(smem + SM_D  )[tid] = g_d  [bi * BM + tid];
        reinterpret_cast<float*>(smem + SM_RNO)[tid] = g_rno[bj * BN + tid];
    }

    const __half* __restrict__ Wt = g_Wh + (size_t)(bi * BM) * D;
    const __half* __restrict__ Ot = g_Oh + (size_t)(bj * BN) * D;

    const int lrow = tid >> 3;     // 0..31 (+32*i)
    const int lcol = tid & 7;

    // fp16 accumulators: acc[f][g] = 2 regs (4 halves)
    uint32_t acc[4][4][2];
    #pragma unroll
    for (int f = 0; f < 4; ++f)
        #pragma unroll
        for (int g = 0; g < 4; ++g)
            acc[f][g][0] = acc[f][g][1] = 0u;

    const int a_row = warp_m * 64 + ((lane >> 3) & 1) * 8 + (lane & 7);
    const int a_cb  = (lane >> 4) * 16;
    const int b_row = warp_n * 32 + ((lane >> 4) & 1) * 8 + (lane & 7);
    const int b_cb  = ((lane >> 3) & 1) * 16;

    // prologue: load chunk 0 into buffer 0
    {
        #pragma unroll
        for (int i = 0; i < 4; ++i) {
            int row = lrow + i * 32;
            cp_async16(sbase + SM_A0 + swz128(row * 128 + lcol * 16),
                       Wt + (size_t)row * D + lcol * 8);
            cp_async16(sbase + SM_B0 + swz128(row * 128 + lcol * 16),
                       Ot + (size_t)row * D + lcol * 8);
        }
        CP_COMMIT();
    }

    #pragma unroll 1
    for (int kc = 0; kc < NKC; ++kc) {
        const int b = kc & 1;
        CP_WAIT0();
        __syncthreads();

        if (kc + 1 < NKC) {
            const int kt = (kc + 1) * BK;
            const uint32_t sa = sbase + (b ? SM_A0 : SM_A1);
            const uint32_t sb = sbase + (b ? SM_B0 : SM_B1);
            #pragma unroll
            for (int i = 0; i < 4; ++i) {
                int row = lrow + i * 32;
                cp_async16(sa + swz128(row * 128 + lcol * 16),
                           Wt + (size_t)row * D + kt + lcol * 8);
                cp_async16(sb + swz128(row * 128 + lcol * 16),
                           Ot + (size_t)row * D + kt + lcol * 8);
            }
            CP_COMMIT();
        }

        const uint32_t abuf = sbase + (b ? SM_A1 : SM_A0);
        const uint32_t bbuf = sbase + (b ? SM_B1 : SM_B0);

        #pragma unroll
        for (int ks = 0; ks < 4; ++ks) {
            uint32_t areg[4][4];
            uint32_t breg[2][4];
            #pragma unroll
            for (int f = 0; f < 4; ++f)
                ldsm_x4(areg[f], abuf + swz128((a_row + f * 16) * 128 + a_cb + ks * 32));
            #pragma unroll
            for (int nf2 = 0; nf2 < 2; ++nf2)
                ldsm_x4(breg[nf2], bbuf + swz128((b_row + nf2 * 16) * 128 + b_cb + ks * 32));
            #pragma unroll
            for (int f = 0; f < 4; ++f)
                #pragma unroll
                for (int g = 0; g < 4; ++g)
                    mma_f16acc(acc[f][g], areg[f], &breg[g >> 1][(g & 1) * 2]);
        }
        __syncthreads();
    }

    // ---- fused epilogue (fp32 normalize, exact fp32 diagonal) ----------------
    const float* srnw = reinterpret_cast<const float*>(smem + SM_RNW);
    const float* sd   = reinterpret_cast<const float*>(smem + SM_D);
    const float* srno = reinterpret_cast<const float*>(smem + SM_RNO);

    const int qrow = lane >> 2;
    const int qcol = (lane & 3) * 2;

    float rno_v[8];
    #pragma unroll
    for (int g = 0; g < 4; ++g)
        #pragma unroll
        for (int e = 0; e < 2; ++e)
            rno_v[g * 2 + e] = srno[warp_n * 32 + g * 8 + qcol + e];

    float lsum = 0.f;
    #pragma unroll
    for (int f = 0; f < 4; ++f) {
        #pragma unroll
        for (int h = 0; h < 2; ++h) {     // reg h: rows qrow + h*8
            const int rl = warp_m * 64 + f * 16 + qrow + h * 8;
            const int rg = bi * BM + rl;
            const float rnw_r = srnw[rl];
            const float d_r   = sd[rl];
            #pragma unroll
            for (int g = 0; g < 4; ++g) {
                const float2 sv = __half22float2(*reinterpret_cast<__half2*>(&acc[f][g][h]));
                #pragma unroll
                for (int e = 0; e < 2; ++e) {
                    const int cl = warp_n * 32 + g * 8 + qcol + e;
                    const int jg = bj * BN + cl;
                    const float S = (e ? sv.y : sv.x) * rnw_r * rno_v[g * 2 + e];
                    lsum += (rg == jg) ? (1.0f - d_r) : fmaxf(MARGIN - S + d_r, 0.0f);
                }
            }
        }
    }

    lsum = warp_sum(lsum);
    __shared__ float red[8];
    if (lane == 0) red[wid] = lsum;
    __syncthreads();
    if (wid == 0) {
        float v = (lane < 8) ? red[lane] : 0.f;
        v = warp_sum(v);
        if (lane == 0) {
            atomicAdd(&g_acc, (double)v);
            __threadfence();
            unsigned int t = atomicAdd(&g_ticket, 1u);
            if (t == NCTAS - 1) {
                double total;
                asm volatile("ld.global.acquire.gpu.f64 %0, [%1];" : "=d"(total) : "l"(&g_acc));
                out[0] = (float)(total / ((double)N * (double)N));
                g_acc = 0.0;
                g_ticket = 0u;
                __threadfence();
            }
        }
    }
}

extern "C" void kernel_launch(void* const* d_in, const int* in_sizes, int n_in,
                              void* d_out, int out_size) {
    const float* W = (const float*)d_in[0];
    const float* O = (const float*)d_in[1];
    float* out = (float*)d_out;

    cudaFuncSetAttribute(gemm_loss_mma, cudaFuncAttributeMaxDynamicSharedMemorySize, SM_TOTAL);

    row_stats_kernel<<<N / 4, 256>>>(W, O);

    dim3 grid(N / BN, N / BM);   // (32, 32)
    gemm_loss_mma<<<grid, 256, SM_TOTAL>>>(out);
}